// round 5
// baseline (speedup 1.0000x reference)
#include <cuda_runtime.h>
#include <cstdint>

#define BATCH  4096
#define DIM    1024
#define TDICT  32768
#define TOPK   64
#define G0_END 2048
#define G1_END 8192

typedef unsigned long long ull;

// ---------------- scratch (device globals: allocation-free) ----------------
static __device__ float g_acts[(size_t)BATCH * TDICT];   // 512 MB relu'd pre-acts
static __device__ float g_topv[BATCH * TOPK];
static __device__ int   g_topi[BATCH * TOPK];

__device__ __forceinline__ void ffma2(ull& d, ull a, ull b) {
    asm("fma.rn.f32x2 %0, %1, %2, %0;" : "+l"(d) : "l"(a), "l"(b));
}
__device__ __forceinline__ ull dup2(float f) {
    ull r; asm("mov.b64 %0, {%1, %1};" : "=l"(r) : "f"(f)); return r;
}
__device__ __forceinline__ float lo32(ull v) { return __uint_as_float((unsigned)(v & 0xffffffffULL)); }
__device__ __forceinline__ float hi32(ull v) { return __uint_as_float((unsigned)(v >> 32)); }

// ============================================================================
// Kernel 1: encoder GEMM  g_acts = relu((x - b_dec) @ W_enc + b_enc)
// Block tile 256m x 128n, BK=8, 256 threads, per-thread 16m x 8n.
// Accumulators packed along m (f32x2 of adjacent m rows) -> A operands load
// packed straight from SMEM (no duplication). B broadcast pairs built with
// movs on the ALU pipe. SMEM traffic: 96 B per 64 FFMA2 per thread.
// ============================================================================
__global__ void __launch_bounds__(256, 1)
enc_gemm_relu(const float* __restrict__ X, const float* __restrict__ W,
              const float* __restrict__ Benc, const float* __restrict__ Bdec)
{
    __shared__ float As[2][8][260];   // [k][m], 256 live + pad
    __shared__ float Bs[2][8][132];   // [k][n], 128 live + pad

    const int tid = threadIdx.x;
    const int bm = blockIdx.x, bn = blockIdx.y;

    // A loader: thread covers rows ar and ar+128, k-halves ak..ak+3
    const int ar = tid >> 1;          // 0..127
    const int ak = (tid & 1) << 2;    // 0 or 4
    // B loader
    const int br = tid >> 5;          // 0..7
    const int bc = (tid & 31) << 2;   // 0..124

    const float* Ap0 = X + (size_t)(bm * 256 + ar) * DIM + ak;
    const float* Ap1 = Ap0 + (size_t)128 * DIM;
    const float* Bp  = W + (size_t)br * TDICT + bn * 128 + bc;

    float4 a0 = *(const float4*)Ap0;
    float4 a1 = *(const float4*)Ap1;
    float4 bd = *(const float4*)(Bdec + ak);
    float4 b  = *(const float4*)Bp;

    As[0][ak + 0][ar]       = a0.x - bd.x;
    As[0][ak + 1][ar]       = a0.y - bd.y;
    As[0][ak + 2][ar]       = a0.z - bd.z;
    As[0][ak + 3][ar]       = a0.w - bd.w;
    As[0][ak + 0][ar + 128] = a1.x - bd.x;
    As[0][ak + 1][ar + 128] = a1.y - bd.y;
    As[0][ak + 2][ar + 128] = a1.z - bd.z;
    As[0][ak + 3][ar + 128] = a1.w - bd.w;
    *(float4*)&Bs[0][br][bc] = b;
    __syncthreads();

    const int tm = (tid & 15) << 2;   // 0..60  (m quadrant offset)
    const int tn = (tid >> 4) << 3;   // 0..120

    ull acc[8][8];
    #pragma unroll
    for (int i = 0; i < 8; i++)
        #pragma unroll
        for (int j = 0; j < 8; j++) acc[i][j] = 0ULL;

    int buf = 0;
    #pragma unroll 1
    for (int kt = 0; kt < 128; ++kt) {
        if (kt < 127) {
            a0 = *(const float4*)(Ap0 + (kt + 1) * 8);
            a1 = *(const float4*)(Ap1 + (kt + 1) * 8);
            bd = *(const float4*)(Bdec + (kt + 1) * 8 + ak);
            b  = *(const float4*)(Bp + (size_t)(kt + 1) * 8 * TDICT);
        }
        #pragma unroll
        for (int k = 0; k < 8; ++k) {
            ulonglong2 A0 = *(const ulonglong2*)&As[buf][k][tm];
            ulonglong2 A1 = *(const ulonglong2*)&As[buf][k][tm + 64];
            ulonglong2 A2 = *(const ulonglong2*)&As[buf][k][tm + 128];
            ulonglong2 A3 = *(const ulonglong2*)&As[buf][k][tm + 192];
            float4 b0 = *(const float4*)&Bs[buf][k][tn];
            float4 b1 = *(const float4*)&Bs[buf][k][tn + 4];
            ull ap[8];
            ap[0] = A0.x; ap[1] = A0.y; ap[2] = A1.x; ap[3] = A1.y;
            ap[4] = A2.x; ap[5] = A2.y; ap[6] = A3.x; ap[7] = A3.y;
            ull bp[8];
            bp[0] = dup2(b0.x); bp[1] = dup2(b0.y);
            bp[2] = dup2(b0.z); bp[3] = dup2(b0.w);
            bp[4] = dup2(b1.x); bp[5] = dup2(b1.y);
            bp[6] = dup2(b1.z); bp[7] = dup2(b1.w);
            #pragma unroll
            for (int i = 0; i < 8; i++)
                #pragma unroll
                for (int j = 0; j < 8; j++) ffma2(acc[i][j], ap[i], bp[j]);
        }
        if (kt < 127) {
            buf ^= 1;
            As[buf][ak + 0][ar]       = a0.x - bd.x;
            As[buf][ak + 1][ar]       = a0.y - bd.y;
            As[buf][ak + 2][ar]       = a0.z - bd.z;
            As[buf][ak + 3][ar]       = a0.w - bd.w;
            As[buf][ak + 0][ar + 128] = a1.x - bd.x;
            As[buf][ak + 1][ar + 128] = a1.y - bd.y;
            As[buf][ak + 2][ar + 128] = a1.z - bd.z;
            As[buf][ak + 3][ar + 128] = a1.w - bd.w;
            *(float4*)&Bs[buf][br][bc] = b;
            __syncthreads();
        }
    }

    // epilogue: + b_enc, relu, store. acc[i][j]: rows m0=64*(i>>1)+tm+2*(i&1)
    // (lo half) and m0+1 (hi half), col = tn + j.
    const float4 be0 = *(const float4*)(Benc + bn * 128 + tn);
    const float4 be1 = *(const float4*)(Benc + bn * 128 + tn + 4);
    const float be[8] = {be0.x, be0.y, be0.z, be0.w, be1.x, be1.y, be1.z, be1.w};
    #pragma unroll
    for (int i = 0; i < 8; i++) {
        const int m0 = ((i >> 1) << 6) + tm + ((i & 1) << 1);
        float* out0 = g_acts + (size_t)(bm * 256 + m0) * TDICT + bn * 128 + tn;
        float* out1 = out0 + TDICT;
        float4 r0, r1, s0, s1;
        r0.x = fmaxf(lo32(acc[i][0]) + be[0], 0.f);
        r0.y = fmaxf(lo32(acc[i][1]) + be[1], 0.f);
        r0.z = fmaxf(lo32(acc[i][2]) + be[2], 0.f);
        r0.w = fmaxf(lo32(acc[i][3]) + be[3], 0.f);
        r1.x = fmaxf(lo32(acc[i][4]) + be[4], 0.f);
        r1.y = fmaxf(lo32(acc[i][5]) + be[5], 0.f);
        r1.z = fmaxf(lo32(acc[i][6]) + be[6], 0.f);
        r1.w = fmaxf(lo32(acc[i][7]) + be[7], 0.f);
        s0.x = fmaxf(hi32(acc[i][0]) + be[0], 0.f);
        s0.y = fmaxf(hi32(acc[i][1]) + be[1], 0.f);
        s0.z = fmaxf(hi32(acc[i][2]) + be[2], 0.f);
        s0.w = fmaxf(hi32(acc[i][3]) + be[3], 0.f);
        s1.x = fmaxf(hi32(acc[i][4]) + be[4], 0.f);
        s1.y = fmaxf(hi32(acc[i][5]) + be[5], 0.f);
        s1.z = fmaxf(hi32(acc[i][6]) + be[6], 0.f);
        s1.w = fmaxf(hi32(acc[i][7]) + be[7], 0.f);
        *(float4*)(out0)     = r0;
        *(float4*)(out0 + 4) = r1;
        *(float4*)(out1)     = s0;
        *(float4*)(out1 + 4) = s1;
    }
}

// ============================================================================
// Kernel 2: exact top-64 per row, 2-pass 12-bit histogram select.
// Pass 1: histogram of (bits >> 20) with warp-aggregated smem atomics.
// Pass 2: collect strictly-greater values (< 64) + pivot-bin candidates
// (expected ~few for gaussian acts; capacity 2048). Exact rank select with
// (value desc, index asc) tie-break == jax.lax.top_k semantics.
// ============================================================================
__global__ void __launch_bounds__(256)
topk_kernel()
{
    __shared__ unsigned hist[4096];
    __shared__ unsigned csum[256];
    __shared__ int s_B, s_C, s_R;
    __shared__ unsigned s_nHi, s_nEq;
    __shared__ float cv[TOPK];
    __shared__ int   ci[TOPK];
    __shared__ unsigned eqV[2048];
    __shared__ int      eqI[2048];

    const int row = blockIdx.x;
    const int tid = threadIdx.x;
    const uint4* src = (const uint4*)(g_acts + (size_t)row * TDICT);

    for (int i = tid; i < 4096; i += 256) hist[i] = 0u;
    if (tid == 0) { s_nHi = 0u; s_nEq = 0u; }
    __syncthreads();

    // ---- pass 1: histogram ----
    for (int j = tid; j < TDICT / 4; j += 256) {
        uint4 v = src[j];
        unsigned bb[4] = {v.x >> 20, v.y >> 20, v.z >> 20, v.w >> 20};
        #pragma unroll
        for (int c = 0; c < 4; c++) {
            unsigned mk = __match_any_sync(0xffffffffu, bb[c]);
            if ((tid & 31) == (__ffs(mk) - 1))
                atomicAdd(&hist[bb[c]], (unsigned)__popc(mk));
        }
    }
    __syncthreads();

    // per-thread chunk sums (16 bins each)
    {
        unsigned s = 0;
        #pragma unroll
        for (int i = 0; i < 16; i++) s += hist[tid * 16 + i];
        csum[tid] = s;
    }
    __syncthreads();

    if (tid == 0) {
        int cum = 0, pc = 0;
        for (int t = 255; t >= 0; --t) {
            if (cum + (int)csum[t] >= TOPK) { pc = t; break; }
            cum += (int)csum[t];
        }
        int B = pc * 16;
        for (int i = 15; i >= 0; --i) {
            int h = (int)hist[pc * 16 + i];
            if (cum + h >= TOPK) { B = pc * 16 + i; break; }
            cum += h;
        }
        s_B = B; s_C = cum; s_R = TOPK - cum;
    }
    __syncthreads();

    const unsigned B = (unsigned)s_B;
    const int C = s_C, R = s_R;

    // ---- pass 2: collect ----
    for (int j = tid; j < TDICT / 4; j += 256) {
        uint4 v = src[j];
        unsigned vv[4] = {v.x, v.y, v.z, v.w};
        const int base = j * 4;
        #pragma unroll
        for (int c = 0; c < 4; c++) {
            unsigned bin = vv[c] >> 20;
            if (bin > B) {
                unsigned p = atomicAdd(&s_nHi, 1u);
                cv[p] = __uint_as_float(vv[c]);
                ci[p] = base + c;
            } else if (bin == B && B != 0u) {
                unsigned q = atomicAdd(&s_nEq, 1u);
                if (q < 2048u) { eqV[q] = vv[c]; eqI[q] = base + c; }
            }
        }
    }
    __syncthreads();

    if (B == 0u) {
        // fewer than 64 positive values: zero-valued fillers with sentinel idx
        if (tid < R) { cv[C + tid] = 0.f; ci[C + tid] = TDICT + tid; }
    } else {
        int nEq = (int)s_nEq; if (nEq > 2048) nEq = 2048;
        for (int t = tid; t < nEq; t += 256) {
            unsigned mv = eqV[t]; int mi = eqI[t];
            int rank = 0;
            for (int u = 0; u < nEq; ++u) {
                unsigned ov = eqV[u]; int oi = eqI[u];
                if (ov > mv || (ov == mv && oi < mi)) rank++;
            }
            if (rank < R) { cv[C + rank] = __uint_as_float(mv); ci[C + rank] = mi; }
        }
    }
    __syncthreads();

    // sort the 64 selected entries by index (all indices distinct)
    if (tid < TOPK) {
        int myI = ci[tid]; float myV = cv[tid];
        int rank = 0;
        #pragma unroll 8
        for (int u = 0; u < TOPK; ++u)
            if (ci[u] < myI) rank++;
        g_topv[row * TOPK + rank] = myV;
        g_topi[row * TOPK + rank] = (myI < TDICT) ? myI : 0;
    }
}

// ============================================================================
// Kernel 3: nested (matryoshka) sparse decode.
// ============================================================================
__global__ void __launch_bounds__(256)
decode_kernel(const float* __restrict__ Wdec, const float* __restrict__ Bdec,
              float* __restrict__ out)
{
    const int row = blockIdx.x;
    const int tid = threadIdx.x;
    __shared__ float sv[TOPK];
    __shared__ int   si[TOPK];
    if (tid < TOPK) {
        sv[tid] = g_topv[row * TOPK + tid];
        si[tid] = g_topi[row * TOPK + tid];
    }
    __syncthreads();

    const int d = tid * 4;
    float4 a0 = make_float4(0.f, 0.f, 0.f, 0.f);
    float4 a1 = a0, a2 = a0;

    #pragma unroll 4
    for (int e = 0; e < TOPK; ++e) {
        float v = sv[e];
        if (v == 0.f) continue;                 // filler / zero entry
        int idx = si[e];
        float4 w = *(const float4*)(Wdec + (size_t)idx * DIM + d);
        if (idx < G0_END) {
            a0.x += v * w.x; a0.y += v * w.y; a0.z += v * w.z; a0.w += v * w.w;
        } else if (idx < G1_END) {
            a1.x += v * w.x; a1.y += v * w.y; a1.z += v * w.z; a1.w += v * w.w;
        } else {
            a2.x += v * w.x; a2.y += v * w.y; a2.z += v * w.z; a2.w += v * w.w;
        }
    }

    float4 bd = *(const float4*)(Bdec + d);
    float4 r0 = make_float4(bd.x + a0.x, bd.y + a0.y, bd.z + a0.z, bd.w + a0.w);
    float4 r1 = make_float4(r0.x + a1.x, r0.y + a1.y, r0.z + a1.z, r0.w + a1.w);
    float4 r2 = make_float4(r1.x + a2.x, r1.y + a2.y, r1.z + a2.z, r1.w + a2.w);

    const size_t stride = (size_t)BATCH * DIM;
    float* o = out + (size_t)row * DIM + d;
    *(float4*)(o)              = r0;
    *(float4*)(o + stride)     = r1;
    *(float4*)(o + 2 * stride) = r2;
}

// ============================================================================
extern "C" void kernel_launch(void* const* d_in, const int* in_sizes, int n_in,
                              void* d_out, int out_size)
{
    const float* x     = (const float*)d_in[0];   // [4096, 1024]
    const float* W_enc = (const float*)d_in[1];   // [1024, 32768]
    const float* b_enc = (const float*)d_in[2];   // [32768]
    const float* W_dec = (const float*)d_in[3];   // [32768, 1024]
    const float* b_dec = (const float*)d_in[4];   // [1024]
    float* out = (float*)d_out;                   // [3, 4096, 1024]

    (void)in_sizes; (void)n_in; (void)out_size;

    dim3 ggrid(BATCH / 256, TDICT / 128);
    enc_gemm_relu<<<ggrid, 256>>>(x, W_enc, b_enc, b_dec);

    topk_kernel<<<BATCH, 256>>>();

    decode_kernel<<<BATCH, 256>>>(W_dec, b_dec, out);
}

// round 7
// speedup vs baseline: 2.7513x; 2.7513x over previous
#include <cuda_runtime.h>
#include <cuda_bf16.h>
#include <cstdint>

#define BATCH  4096
#define DIM    1024
#define TDICT  32768
#define TOPK   64
#define NCAND  96
#define G0_END 2048
#define G1_END 8192

#define BM 128
#define BN 128
#define BK 32
#define NKT (DIM / BK)
#define ROWH 40                         // halves per smem row (80B, conflict-free ldmatrix)
#define SSTRIDE (2 * BM * ROWH)         // halves per stage (A tile + B tile)
#define GEMM_SMEM (3 * SSTRIDE * 2)     // 61440 bytes

typedef unsigned long long ull;

// ---------------- scratch (device globals: allocation-free) ----------------
static __device__ float         g_acts[(size_t)BATCH * TDICT];  // approx relu'd pre-acts
static __device__ float         g_AX[(size_t)BATCH * DIM];      // exact x - b_dec
static __device__ __nv_bfloat16 g_Abf[(size_t)BATCH * DIM];
static __device__ float         g_BT[(size_t)TDICT * DIM];      // exact W_enc^T
static __device__ __nv_bfloat16 g_Bbf[(size_t)TDICT * DIM];     // bf16 W_enc^T
static __device__ int           g_cand[(size_t)BATCH * NCAND];
static __device__ float         g_topv[BATCH * TOPK];
static __device__ int           g_topi[BATCH * TOPK];

__device__ __forceinline__ uint32_t su32(const void* p) {
    uint32_t a;
    asm("{ .reg .u64 t; cvta.to.shared.u64 t, %1; cvt.u32.u64 %0, t; }" : "=r"(a) : "l"(p));
    return a;
}
__device__ __forceinline__ void cpa16(uint32_t s, const void* g) {
    asm volatile("cp.async.cg.shared.global [%0], [%1], 16;" :: "r"(s), "l"(g));
}
__device__ __forceinline__ void ldsm4(uint32_t* r, uint32_t addr) {
    asm volatile("ldmatrix.sync.aligned.m8n8.x4.shared.b16 {%0,%1,%2,%3}, [%4];"
        : "=r"(r[0]), "=r"(r[1]), "=r"(r[2]), "=r"(r[3]) : "r"(addr));
}
__device__ __forceinline__ void mma_bf16(float* d, const uint32_t* a, uint32_t b0, uint32_t b1) {
    asm volatile("mma.sync.aligned.m16n8k16.row.col.f32.bf16.bf16.f32 "
        "{%0,%1,%2,%3}, {%4,%5,%6,%7}, {%8,%9}, {%0,%1,%2,%3};"
        : "+f"(d[0]), "+f"(d[1]), "+f"(d[2]), "+f"(d[3])
        : "r"(a[0]), "r"(a[1]), "r"(a[2]), "r"(a[3]), "r"(b0), "r"(b1));
}

// ---- converter A: exact fp32 x_cent + bf16 copy ----
__global__ void __launch_bounds__(256)
conv_A(const float* __restrict__ X, const float* __restrict__ Bdec)
{
    int i = blockIdx.x * 256 + threadIdx.x;   // BATCH*DIM/4 float4s
    int row = i >> 8, kp = (i & 255) * 4;
    float4 x  = *(const float4*)(X + (size_t)row * DIM + kp);
    float4 bd = *(const float4*)(Bdec + kp);
    x.x -= bd.x; x.y -= bd.y; x.z -= bd.z; x.w -= bd.w;
    *(float4*)(g_AX + (size_t)row * DIM + kp) = x;
    ushort4 h;
    h.x = __bfloat16_as_ushort(__float2bfloat16(x.x));
    h.y = __bfloat16_as_ushort(__float2bfloat16(x.y));
    h.z = __bfloat16_as_ushort(__float2bfloat16(x.z));
    h.w = __bfloat16_as_ushort(__float2bfloat16(x.w));
    *(ushort4*)(g_Abf + (size_t)row * DIM + kp) = h;
}

// ---- converter B: transpose W_enc [K][N] -> fp32 + bf16 [n][k] ----
__global__ void __launch_bounds__(256)
conv_BT(const float* __restrict__ W)
{
    __shared__ float t[64][65];
    const int tid = threadIdx.x;
    const int n0 = blockIdx.x * 64, k0 = blockIdx.y * 64;
    #pragma unroll
    for (int it = 0; it < 16; ++it) {
        int li = it * 256 + tid, kk = li >> 6, nn = li & 63;
        t[kk][nn] = W[(size_t)(k0 + kk) * TDICT + n0 + nn];
    }
    __syncthreads();
    #pragma unroll
    for (int it = 0; it < 16; ++it) {
        int li = it * 256 + tid, nn = li >> 6, kk = li & 63;
        float v = t[kk][nn];
        g_BT[(size_t)(n0 + nn) * DIM + k0 + kk]  = v;
        g_Bbf[(size_t)(n0 + nn) * DIM + k0 + kk] = __float2bfloat16(v);
    }
}

// ---- bf16 mma.sync GEMM: g_acts = relu(A_bf @ B_bf^T + b_enc) ----
__global__ void __launch_bounds__(256)
enc_gemm_bf16(const float* __restrict__ Benc)
{
    extern __shared__ __align__(16) uint16_t sm[];
    const int tid = threadIdx.x, lane = tid & 31, wid = tid >> 5;
    const int bm = blockIdx.x, bn = blockIdx.y;
    const int m0 = (wid >> 2) * 64, n0 = (wid & 3) * 32;
    const uint32_t sb = su32(sm);

    auto ldstage = [&](int s, int kt) {
        #pragma unroll
        for (int i = 0; i < 2; ++i) {
            int c = tid + i * 256;
            int row = c >> 2, kc = c & 3;
            cpa16(sb + (s * SSTRIDE + row * ROWH + kc * 8) * 2,
                  g_Abf + (size_t)(bm * BM + row) * DIM + kt * BK + kc * 8);
            cpa16(sb + (s * SSTRIDE + BM * ROWH + row * ROWH + kc * 8) * 2,
                  g_Bbf + (size_t)(bn * BN + row) * DIM + kt * BK + kc * 8);
        }
        asm volatile("cp.async.commit_group;" ::: "memory");
    };

    ldstage(0, 0);
    ldstage(1, 1);

    float acc[4][4][4];
    #pragma unroll
    for (int a = 0; a < 4; a++)
        #pragma unroll
        for (int b = 0; b < 4; b++)
            #pragma unroll
            for (int c = 0; c < 4; c++) acc[a][b][c] = 0.f;

    const int arow = m0 + (lane & 15);
    const int acol = (lane >> 4) << 3;
    const int brow = n0 + (lane & 7) + ((lane >> 3) & 1) * 8;

    #pragma unroll 1
    for (int kt = 0; kt < NKT; ++kt) {
        if (kt < NKT - 2) asm volatile("cp.async.wait_group 1;" ::: "memory");
        else              asm volatile("cp.async.wait_group 0;" ::: "memory");
        __syncthreads();
        if (kt + 2 < NKT) ldstage((kt + 2) % 3, kt + 2);

        const int s = kt % 3;
        const uint32_t aB = sb + (s * SSTRIDE) * 2;
        const uint32_t bB = sb + (s * SSTRIDE + BM * ROWH) * 2;
        #pragma unroll
        for (int ks = 0; ks < 2; ++ks) {
            uint32_t af[4][4], bf[2][4];
            #pragma unroll
            for (int mt = 0; mt < 4; ++mt)
                ldsm4(af[mt], aB + ((arow + mt * 16) * ROWH + ks * 16 + acol) * 2);
            #pragma unroll
            for (int nt = 0; nt < 2; ++nt)
                ldsm4(bf[nt], bB + ((brow + nt * 16) * ROWH + ks * 16 + acol) * 2);
            #pragma unroll
            for (int mt = 0; mt < 4; ++mt)
                #pragma unroll
                for (int j = 0; j < 4; ++j)
                    mma_bf16(acc[mt][j], af[mt], bf[j >> 1][j & 1], bf[j >> 1][(j & 1) + 2]);
        }
    }

    // epilogue: + b_enc, relu, store
    #pragma unroll
    for (int mt = 0; mt < 4; ++mt) {
        const int r_lo = bm * BM + m0 + mt * 16 + (lane >> 2);
        #pragma unroll
        for (int j = 0; j < 4; ++j) {
            const int gc = bn * BN + n0 + j * 8 + (lane & 3) * 2;
            const float b0 = Benc[gc], b1 = Benc[gc + 1];
            float2 lo = make_float2(fmaxf(acc[mt][j][0] + b0, 0.f),
                                    fmaxf(acc[mt][j][1] + b1, 0.f));
            float2 hi = make_float2(fmaxf(acc[mt][j][2] + b0, 0.f),
                                    fmaxf(acc[mt][j][3] + b1, 0.f));
            *(float2*)&g_acts[(size_t)r_lo * TDICT + gc]       = lo;
            *(float2*)&g_acts[(size_t)(r_lo + 8) * TDICT + gc] = hi;
        }
    }
}

// ---- candidate selection: approx top-96 per row (indices only) ----
__global__ void __launch_bounds__(256)
cand_kernel()
{
    __shared__ unsigned hist[4096];
    __shared__ unsigned csum[256];
    __shared__ int s_B, s_C, s_R;
    __shared__ unsigned s_nHi, s_nEq;
    __shared__ int ci2[NCAND];
    __shared__ unsigned eqV[2048];
    __shared__ int      eqI[2048];

    const int row = blockIdx.x, tid = threadIdx.x;
    const uint4* src = (const uint4*)(g_acts + (size_t)row * TDICT);

    for (int i = tid; i < 4096; i += 256) hist[i] = 0u;
    if (tid == 0) { s_nHi = 0u; s_nEq = 0u; }
    __syncthreads();

    for (int j = tid; j < TDICT / 4; j += 256) {
        uint4 v = src[j];
        unsigned bb[4] = {v.x >> 20, v.y >> 20, v.z >> 20, v.w >> 20};
        #pragma unroll
        for (int c = 0; c < 4; c++) {
            unsigned mk = __match_any_sync(0xffffffffu, bb[c]);
            if ((tid & 31) == (__ffs(mk) - 1))
                atomicAdd(&hist[bb[c]], (unsigned)__popc(mk));
        }
    }
    __syncthreads();
    {
        unsigned s = 0;
        #pragma unroll
        for (int i = 0; i < 16; i++) s += hist[tid * 16 + i];
        csum[tid] = s;
    }
    __syncthreads();
    if (tid == 0) {
        int cum = 0, pc = 0;
        for (int t = 255; t >= 0; --t) {
            if (cum + (int)csum[t] >= NCAND) { pc = t; break; }
            cum += (int)csum[t];
        }
        int B = pc * 16;
        for (int i = 15; i >= 0; --i) {
            int h = (int)hist[pc * 16 + i];
            if (cum + h >= NCAND) { B = pc * 16 + i; break; }
            cum += h;
        }
        s_B = B; s_C = cum; s_R = NCAND - cum;
    }
    __syncthreads();
    const unsigned B = (unsigned)s_B;
    const int C = s_C, R = s_R;

    for (int j = tid; j < TDICT / 4; j += 256) {
        uint4 v = src[j];
        unsigned vv[4] = {v.x, v.y, v.z, v.w};
        const int base = j * 4;
        #pragma unroll
        for (int c = 0; c < 4; c++) {
            unsigned bin = vv[c] >> 20;
            if (bin > B) {
                unsigned p = atomicAdd(&s_nHi, 1u);
                ci2[p] = base + c;
            } else if (bin == B && B != 0u) {
                unsigned q = atomicAdd(&s_nEq, 1u);
                if (q < 2048u) { eqV[q] = vv[c]; eqI[q] = base + c; }
            }
        }
    }
    __syncthreads();

    if (B == 0u) {
        if (tid < R) ci2[C + tid] = TDICT + tid;     // sentinel fillers
    } else {
        int nEq = (int)s_nEq; if (nEq > 2048) nEq = 2048;
        for (int t = tid; t < nEq; t += 256) {
            unsigned mv = eqV[t]; int mi = eqI[t];
            int rank = 0;
            for (int u = 0; u < nEq; ++u) {
                unsigned ov = eqV[u]; int oi = eqI[u];
                if (ov > mv || (ov == mv && oi < mi)) rank++;
            }
            if (rank < R) ci2[C + rank] = mi;
        }
    }
    __syncthreads();
    if (tid < NCAND) g_cand[row * NCAND + tid] = ci2[tid];
}

// ---- exact fp32 rescoring of candidates + exact top-64 select ----
__global__ void __launch_bounds__(256)
rescore_kernel(const float* __restrict__ Benc)
{
    __shared__ float xs[DIM];
    __shared__ float rv[NCAND];
    __shared__ int   ri[NCAND];
    __shared__ unsigned char keep[NCAND];

    const int row = blockIdx.x, tid = threadIdx.x, lane = tid & 31, wid = tid >> 5;
    *(float4*)&xs[tid * 4] = *(const float4*)&g_AX[(size_t)row * DIM + tid * 4];
    __syncthreads();

    for (int c = wid; c < NCAND; c += 8) {
        int n = g_cand[row * NCAND + c];
        float v = 0.f;
        if (n < TDICT) {
            const float* bt = g_BT + (size_t)n * DIM;
            float s = 0.f;
            #pragma unroll
            for (int it = 0; it < 8; ++it) {
                int k = it * 128 + lane * 4;
                float4 a = *(const float4*)&xs[k];
                float4 b = *(const float4*)&bt[k];
                s += a.x * b.x + a.y * b.y + a.z * b.z + a.w * b.w;
            }
            #pragma unroll
            for (int o = 16; o; o >>= 1) s += __shfl_down_sync(0xffffffffu, s, o);
            if (lane == 0) v = fmaxf(s + Benc[n], 0.f);
        }
        if (lane == 0) { rv[c] = v; ri[c] = n; }
    }
    __syncthreads();

    if (tid < NCAND) {
        float v = rv[tid]; int id = ri[tid];
        int rank = 0;
        for (int u = 0; u < NCAND; ++u) {
            float vu = rv[u]; int iu = ri[u];
            if (vu > v || (vu == v && iu < id)) rank++;
        }
        keep[tid] = (rank < TOPK) ? 1 : 0;
    }
    __syncthreads();
    if (tid < NCAND && keep[tid]) {
        int id = ri[tid];
        int r2 = 0;
        for (int u = 0; u < NCAND; ++u)
            if (keep[u] && ri[u] < id) r2++;
        g_topv[row * TOPK + r2] = rv[tid];
        g_topi[row * TOPK + r2] = (id < TDICT) ? id : 0;
    }
}

// ---- nested (matryoshka) sparse decode ----
__global__ void __launch_bounds__(256)
decode_kernel(const float* __restrict__ Wdec, const float* __restrict__ Bdec,
              float* __restrict__ out)
{
    const int row = blockIdx.x, tid = threadIdx.x;
    __shared__ float sv[TOPK];
    __shared__ int   si[TOPK];
    if (tid < TOPK) {
        sv[tid] = g_topv[row * TOPK + tid];
        si[tid] = g_topi[row * TOPK + tid];
    }
    __syncthreads();

    const int d = tid * 4;
    float4 a0 = make_float4(0.f, 0.f, 0.f, 0.f), a1 = a0, a2 = a0;

    #pragma unroll 4
    for (int e = 0; e < TOPK; ++e) {
        float v = sv[e];
        if (v == 0.f) continue;
        int idx = si[e];
        float4 w = *(const float4*)(Wdec + (size_t)idx * DIM + d);
        if (idx < G0_END) {
            a0.x += v * w.x; a0.y += v * w.y; a0.z += v * w.z; a0.w += v * w.w;
        } else if (idx < G1_END) {
            a1.x += v * w.x; a1.y += v * w.y; a1.z += v * w.z; a1.w += v * w.w;
        } else {
            a2.x += v * w.x; a2.y += v * w.y; a2.z += v * w.z; a2.w += v * w.w;
        }
    }

    float4 bd = *(const float4*)(Bdec + d);
    float4 r0 = make_float4(bd.x + a0.x, bd.y + a0.y, bd.z + a0.z, bd.w + a0.w);
    float4 r1 = make_float4(r0.x + a1.x, r0.y + a1.y, r0.z + a1.z, r0.w + a1.w);
    float4 r2 = make_float4(r1.x + a2.x, r1.y + a2.y, r1.z + a2.z, r1.w + a2.w);

    const size_t stride = (size_t)BATCH * DIM;
    float* o = out + (size_t)row * DIM + d;
    *(float4*)(o) = r0; *(float4*)(o + stride) = r1; *(float4*)(o + 2 * stride) = r2;
}

extern "C" void kernel_launch(void* const* d_in, const int* in_sizes, int n_in,
                              void* d_out, int out_size)
{
    const float* x     = (const float*)d_in[0];   // [4096, 1024]
    const float* W_enc = (const float*)d_in[1];   // [1024, 32768]
    const float* b_enc = (const float*)d_in[2];   // [32768]
    const float* W_dec = (const float*)d_in[3];   // [32768, 1024]
    const float* b_dec = (const float*)d_in[4];   // [1024]
    float* out = (float*)d_out;                   // [3, 4096, 1024]
    (void)in_sizes; (void)n_in; (void)out_size;

    cudaFuncSetAttribute(enc_gemm_bf16, cudaFuncAttributeMaxDynamicSharedMemorySize, GEMM_SMEM);

    conv_A<<<BATCH, 256>>>(x, b_dec);
    conv_BT<<<dim3(TDICT / 64, DIM / 64), 256>>>(W_enc);
    enc_gemm_bf16<<<dim3(BATCH / BM, TDICT / BN), 256, GEMM_SMEM>>>(b_enc);
    cand_kernel<<<BATCH, 256>>>();
    rescore_kernel<<<BATCH, 256>>>(b_enc);
    decode_kernel<<<BATCH, 256>>>(W_dec, b_dec, out);
}